// round 2
// baseline (speedup 1.0000x reference)
#include <cuda_runtime.h>
#include <math.h>
#include <float.h>
#include <stdint.h>

#define HID 128
#define MAX_NODES 50000
#define MAX_EDGES 800000

// ------------------------- scratch (static, no allocs) -------------------------
__device__ float g_A[MAX_NODES * HID];     // z @ Wd
__device__ float g_B[MAX_NODES * HID];     // z @ Ws
__device__ float g_R[MAX_NODES * HID];     // z @ W1a
__device__ float g_agg[MAX_NODES * HID];
__device__ float g_hid[MAX_NODES * HID];
__device__ int   g_deg[MAX_NODES];
__device__ int   g_off[MAX_NODES + 1];
__device__ int   g_cur[MAX_NODES];
__device__ int   g_csr[MAX_EDGES];

// ------------------------- SGEMM: C[M,128] = A[M,128] @ W[128,128] -------------------------
// optional: + add[M,128] + bias[128], relu
#define BM 64
#define BK 16
#define TM 4
#define TN 8

__global__ __launch_bounds__(256) void sgemm_k(
    const float* __restrict__ A, const float* __restrict__ W,
    const float* __restrict__ add, const float* __restrict__ bias,
    float* __restrict__ C, int M, int relu)
{
    __shared__ float As[BK][BM];
    __shared__ float Bs[BK][HID + 4];
    const int tid = threadIdx.x;
    const int tx = tid & 15;     // 0..15 -> cols
    const int ty = tid >> 4;     // 0..15 -> rows
    const int rowBase = blockIdx.x * BM;

    float acc[TM][TN];
#pragma unroll
    for (int i = 0; i < TM; i++)
#pragma unroll
        for (int j = 0; j < TN; j++) acc[i][j] = 0.f;

    const int arow = tid >> 2;        // 0..63
    const int acol = (tid & 3) * 4;   // 0,4,8,12
    const int brow = tid >> 4;        // 0..15
    const int bcol = (tid & 15) * 8;  // 0..120

    for (int k0 = 0; k0 < HID; k0 += BK) {
        const int gr = rowBase + arow;
        float4 av = make_float4(0.f, 0.f, 0.f, 0.f);
        if (gr < M) av = *(const float4*)(A + (size_t)gr * HID + k0 + acol);
        As[acol + 0][arow] = av.x;
        As[acol + 1][arow] = av.y;
        As[acol + 2][arow] = av.z;
        As[acol + 3][arow] = av.w;
        const float4 b0 = *(const float4*)(W + (size_t)(k0 + brow) * HID + bcol);
        const float4 b1 = *(const float4*)(W + (size_t)(k0 + brow) * HID + bcol + 4);
        *(float4*)&Bs[brow][bcol] = b0;
        *(float4*)&Bs[brow][bcol + 4] = b1;
        __syncthreads();
#pragma unroll
        for (int k = 0; k < BK; k++) {
            const float4 aa = *(const float4*)&As[k][ty * TM];
            const float4 bb0 = *(const float4*)&Bs[k][tx * TN];
            const float4 bb1 = *(const float4*)&Bs[k][tx * TN + 4];
            const float a0 = aa.x, a1 = aa.y, a2 = aa.z, a3 = aa.w;
            float b[TN] = {bb0.x, bb0.y, bb0.z, bb0.w, bb1.x, bb1.y, bb1.z, bb1.w};
#pragma unroll
            for (int j = 0; j < TN; j++) {
                acc[0][j] = fmaf(a0, b[j], acc[0][j]);
                acc[1][j] = fmaf(a1, b[j], acc[1][j]);
                acc[2][j] = fmaf(a2, b[j], acc[2][j]);
                acc[3][j] = fmaf(a3, b[j], acc[3][j]);
            }
        }
        __syncthreads();
    }

    float4 bias0 = make_float4(0.f, 0.f, 0.f, 0.f);
    float4 bias1 = make_float4(0.f, 0.f, 0.f, 0.f);
    if (bias) {
        bias0 = *(const float4*)(bias + tx * TN);
        bias1 = *(const float4*)(bias + tx * TN + 4);
    }
#pragma unroll
    for (int i = 0; i < TM; i++) {
        const int r = rowBase + ty * TM + i;
        if (r >= M) continue;
        float v[8];
#pragma unroll
        for (int j = 0; j < 8; j++) v[j] = acc[i][j];
        if (add) {
            const float* ap = add + (size_t)r * HID + tx * TN;
            const float4 s0 = *(const float4*)ap;
            const float4 s1 = *(const float4*)(ap + 4);
            v[0] += s0.x; v[1] += s0.y; v[2] += s0.z; v[3] += s0.w;
            v[4] += s1.x; v[5] += s1.y; v[6] += s1.z; v[7] += s1.w;
        }
        v[0] += bias0.x; v[1] += bias0.y; v[2] += bias0.z; v[3] += bias0.w;
        v[4] += bias1.x; v[5] += bias1.y; v[6] += bias1.z; v[7] += bias1.w;
        if (relu) {
#pragma unroll
            for (int j = 0; j < 8; j++) v[j] = fmaxf(v[j], 0.f);
        }
        float* cp = C + (size_t)r * HID + tx * TN;
        *(float4*)cp = make_float4(v[0], v[1], v[2], v[3]);
        *(float4*)(cp + 4) = make_float4(v[4], v[5], v[6], v[7]);
    }
}

// ------------------------- CSR build -------------------------
__global__ void zero_deg_kernel(int nNodes)
{
    int i = blockIdx.x * blockDim.x + threadIdx.x;
    if (i < nNodes) g_deg[i] = 0;
}

__global__ void deg_kernel(const int* __restrict__ dst, int nE)
{
    int e = blockIdx.x * blockDim.x + threadIdx.x;
    if (e < nE) atomicAdd(&g_deg[dst[e]], 1);
}

// single-block exclusive scan of g_deg -> g_off (and g_cur copy)
__global__ __launch_bounds__(1024) void scan_kernel(int nNodes)
{
    __shared__ int warpPre[32];   // exclusive prefix of warp sums
    __shared__ int s_carry;
    const int tid = threadIdx.x;
    const int lane = tid & 31;
    const int wid = tid >> 5;
    if (tid == 0) s_carry = 0;
    __syncthreads();
    const int nChunks = (nNodes + 1023) >> 10;
    for (int c = 0; c < nChunks; c++) {
        const int i = (c << 10) + tid;
        const int v = (i < nNodes) ? g_deg[i] : 0;
        int incl = v;
#pragma unroll
        for (int o = 1; o < 32; o <<= 1) {
            int t = __shfl_up_sync(0xffffffffu, incl, o);
            if (lane >= o) incl += t;
        }
        if (lane == 31) warpPre[wid] = incl;
        __syncthreads();
        if (wid == 0) {
            int ws = warpPre[lane];
            int wincl = ws;
#pragma unroll
            for (int o = 1; o < 32; o <<= 1) {
                int t = __shfl_up_sync(0xffffffffu, wincl, o);
                if (lane >= o) wincl += t;
            }
            warpPre[lane] = wincl - ws;  // exclusive
        }
        __syncthreads();
        const int excl = s_carry + warpPre[wid] + incl - v;
        if (i < nNodes) { g_off[i] = excl; g_cur[i] = excl; }
        __syncthreads();
        if (tid == 1023) s_carry = excl + v;  // inclusive prefix through last element
        __syncthreads();
    }
    if (tid == 0) g_off[nNodes] = s_carry;
}

__global__ void scatter_kernel(const int* __restrict__ dst, int nE)
{
    int e = blockIdx.x * blockDim.x + threadIdx.x;
    if (e < nE) {
        int p = atomicAdd(&g_cur[dst[e]], 1);
        g_csr[p] = e;
    }
}

// ------------------------- per-node gather-max -------------------------
// agg[n] = deg>0 ? A[n] + bm + max_e (B[src[e]] + w[e]*ww) : 0
__global__ __launch_bounds__(256) void agg_kernel(
    const int* __restrict__ src, const float* __restrict__ ew,
    const float* __restrict__ Wm, const float* __restrict__ bm,
    int nNodes)
{
    const int warpId = (blockIdx.x * blockDim.x + threadIdx.x) >> 5;
    const int lane = threadIdx.x & 31;
    if (warpId >= nNodes) return;
    const int n = warpId;
    const float4 ww4 = *(const float4*)(Wm + 256 * HID + lane * 4);
    const int s0 = g_off[n], s1 = g_off[n + 1];
    float4 m = make_float4(-FLT_MAX, -FLT_MAX, -FLT_MAX, -FLT_MAX);
    for (int base = s0; base < s1; base += 32) {
        const int idx = base + lane;
        int sv = 0; float wv = 0.f;
        if (idx < s1) {
            const int e = g_csr[idx];
            sv = src[e];
            wv = ew[e];
        }
        const int cnt = min(32, s1 - base);
        for (int j = 0; j < cnt; j++) {
            const int sj = __shfl_sync(0xffffffffu, sv, j);
            const float wj = __shfl_sync(0xffffffffu, wv, j);
            const float4 b4 = *(const float4*)(g_B + (size_t)sj * HID + lane * 4);
            m.x = fmaxf(m.x, fmaf(wj, ww4.x, b4.x));
            m.y = fmaxf(m.y, fmaf(wj, ww4.y, b4.y));
            m.z = fmaxf(m.z, fmaf(wj, ww4.z, b4.z));
            m.w = fmaxf(m.w, fmaf(wj, ww4.w, b4.w));
        }
    }
    float4 o;
    if (s1 > s0) {
        const float4 a4 = *(const float4*)(g_A + (size_t)n * HID + lane * 4);
        const float4 bm4 = *(const float4*)(bm + lane * 4);
        o = make_float4(a4.x + bm4.x + m.x, a4.y + bm4.y + m.y,
                        a4.z + bm4.z + m.z, a4.w + bm4.w + m.w);
    } else {
        o = make_float4(0.f, 0.f, 0.f, 0.f);
    }
    *(float4*)(g_agg + (size_t)n * HID + lane * 4) = o;
}

// ------------------------- launch -------------------------
extern "C" void kernel_launch(void* const* d_in, const int* in_sizes, int n_in,
                              void* d_out, int out_size)
{
    const float* z   = (const float*)d_in[0];
    const float* ew  = (const float*)d_in[1];
    const int*   esrc= (const int*)d_in[2];
    const int*   edst= (const int*)d_in[3];
    const float* Wm  = (const float*)d_in[4];
    const float* bm  = (const float*)d_in[5];
    const float* W1  = (const float*)d_in[6];
    const float* b1  = (const float*)d_in[7];
    const float* W2  = (const float*)d_in[8];
    const float* b2  = (const float*)d_in[9];
    float* out = (float*)d_out;

    const int nNodes = in_sizes[0] / HID;
    const int nEdges = in_sizes[1];

    float *pA, *pB, *pR, *pAgg, *pHid;
    cudaGetSymbolAddress((void**)&pA,   g_A);
    cudaGetSymbolAddress((void**)&pB,   g_B);
    cudaGetSymbolAddress((void**)&pR,   g_R);
    cudaGetSymbolAddress((void**)&pAgg, g_agg);
    cudaGetSymbolAddress((void**)&pHid, g_hid);

    const int gemmGrid = (nNodes + BM - 1) / BM;
    const int edgeGrid = (nEdges + 255) / 256;
    const int nodeGrid = (nNodes + 255) / 256;
    const int aggGrid  = (nNodes + 7) / 8;   // 8 warps/block, warp per node

    // CSR build
    zero_deg_kernel<<<nodeGrid, 256>>>(nNodes);
    deg_kernel<<<edgeGrid, 256>>>(edst, nEdges);
    scan_kernel<<<1, 1024>>>(nNodes);
    scatter_kernel<<<edgeGrid, 256>>>(edst, nEdges);

    // node-feature GEMMs: A = z@Wd, B = z@Ws, R = z@W1a
    sgemm_k<<<gemmGrid, 256>>>(z, Wm,             nullptr, nullptr, pA, nNodes, 0);
    sgemm_k<<<gemmGrid, 256>>>(z, Wm + 128 * HID, nullptr, nullptr, pB, nNodes, 0);
    sgemm_k<<<gemmGrid, 256>>>(z, W1,             nullptr, nullptr, pR, nNodes, 0);

    // segment max (gather form)
    agg_kernel<<<aggGrid, 256>>>(esrc, ew, Wm, bm, nNodes);

    // hidden = relu(R + agg@W1b + b1)
    sgemm_k<<<gemmGrid, 256>>>(pAgg, W1 + 128 * HID, pR, b1, pHid, nNodes, 1);
    // out = hidden@W2 + b2
    sgemm_k<<<gemmGrid, 256>>>(pHid, W2, nullptr, b2, out, nNodes, 0);
}

// round 4
// speedup vs baseline: 1.7073x; 1.7073x over previous
#include <cuda_runtime.h>
#include <math.h>
#include <float.h>
#include <stdint.h>

#define HID 128
#define MAX_NODES 50000
#define MAX_EDGES 800000

// ------------------------- scratch (static, no allocs) -------------------------
__device__ float g_A[MAX_NODES * HID];     // z @ Wd
__device__ float g_B[MAX_NODES * HID];     // z @ Ws
__device__ float g_R[MAX_NODES * HID];     // z @ W1a
__device__ float g_agg[MAX_NODES * HID];
__device__ float g_hid[MAX_NODES * HID];
__device__ int   g_deg[MAX_NODES];
__device__ int   g_off[MAX_NODES + 1];
__device__ int   g_cur[MAX_NODES];
__device__ int   g_csr[MAX_EDGES];

// ------------------------- tf32 helpers (sm_80+ baseline PTX only) -------------------------
__device__ __forceinline__ uint32_t f2tf(float f) {
    uint32_t u;
    asm("cvt.rna.tf32.f32 %0, %1;" : "=r"(u) : "f"(f));
    return u;
}

__device__ __forceinline__ void mma_tf32(float* c, const uint32_t* a, uint32_t b0, uint32_t b1) {
    asm volatile(
        "mma.sync.aligned.m16n8k8.row.col.f32.tf32.tf32.f32 "
        "{%0,%1,%2,%3}, {%4,%5,%6,%7}, {%8,%9}, {%0,%1,%2,%3};"
        : "+f"(c[0]), "+f"(c[1]), "+f"(c[2]), "+f"(c[3])
        : "r"(a[0]), "r"(a[1]), "r"(a[2]), "r"(a[3]), "r"(b0), "r"(b1));
}

// ------------------------- tf32 GEMM: C[M,128] = A[M,128] @ W[128,128] -------------------------
// CTA = 256 threads = 8 warps (4 x 2), tile 128(M) x 128(N), K looped in BK=64 chunks.
// A smem: row-major [128][PA], fragment loads conflict-free (banks g*4+tg).
// B smem: k-major   [64][PB],  fragment loads conflict-free (banks tg*8+g).
#define BKC 64
#define PA  68
#define PB  136
#define GEMM_SMEM_BYTES ((128 * PA + BKC * PB) * 4)

__device__ __forceinline__ void gemm_body(
    const float* __restrict__ A, const float* __restrict__ W,
    const float* __restrict__ add, const float* __restrict__ bias,
    float* __restrict__ C, int M, int relu, int rowBase)
{
    extern __shared__ uint32_t smem[];
    uint32_t* As = smem;                 // [128][PA]
    uint32_t* Bs = smem + 128 * PA;      // [BKC][PB]

    const int tid  = threadIdx.x;
    const int wid  = tid >> 5;
    const int lane = tid & 31;
    const int g    = lane >> 2;   // 0..7
    const int tg   = lane & 3;    // 0..3
    const int wm   = (wid & 3) << 5;   // warp M offset: 0,32,64,96
    const int wn   = (wid >> 2) << 6;  // warp N offset: 0,64

    float acc[2][8][4];
#pragma unroll
    for (int mt = 0; mt < 2; mt++)
#pragma unroll
        for (int nt = 0; nt < 8; nt++)
#pragma unroll
            for (int i = 0; i < 4; i++) acc[mt][nt][i] = 0.f;

    for (int k0 = 0; k0 < HID; k0 += BKC) {
        // ---- load A chunk [128 rows][64 k] as tf32 ----
#pragma unroll
        for (int it = 0; it < 8; it++) {
            const int i = it * 256 + tid;
            const int row = i >> 4;             // 0..127
            const int c4  = (i & 15) << 2;      // 0,4,...,60
            const int gr = rowBase + row;
            float4 v = make_float4(0.f, 0.f, 0.f, 0.f);
            if (gr < M) v = *(const float4*)(A + (size_t)gr * HID + k0 + c4);
            uint32_t* p = As + row * PA + c4;
            p[0] = f2tf(v.x); p[1] = f2tf(v.y); p[2] = f2tf(v.z); p[3] = f2tf(v.w);
        }
        // ---- load B chunk: Bs[k][n] = W[k0+k][n], k-major, coalesced ----
#pragma unroll
        for (int it = 0; it < 8; it++) {
            const int i = it * 256 + tid;
            const int k  = i >> 5;              // 0..63
            const int n4 = (i & 31) << 2;       // 0,4,...,124
            const float4 v = *(const float4*)(W + (size_t)(k0 + k) * HID + n4);
            uint32_t* p = Bs + k * PB + n4;
            p[0] = f2tf(v.x); p[1] = f2tf(v.y); p[2] = f2tf(v.z); p[3] = f2tf(v.w);
        }
        __syncthreads();

        // ---- compute: 8 k8-steps ----
#pragma unroll
        for (int kk = 0; kk < BKC; kk += 8) {
            uint32_t a[2][4];
#pragma unroll
            for (int mt = 0; mt < 2; mt++) {
                const uint32_t* ap = As + (wm + mt * 16 + g) * PA + kk + tg;
                a[mt][0] = ap[0];
                a[mt][1] = ap[8 * PA];
                a[mt][2] = ap[4];
                a[mt][3] = ap[8 * PA + 4];
            }
#pragma unroll
            for (int nt = 0; nt < 8; nt++) {
                const uint32_t b0 = Bs[(kk + tg) * PB + wn + nt * 8 + g];
                const uint32_t b1 = Bs[(kk + tg + 4) * PB + wn + nt * 8 + g];
                mma_tf32(acc[0][nt], a[0], b0, b1);
                mma_tf32(acc[1][nt], a[1], b0, b1);
            }
        }
        __syncthreads();
    }

    // ---- epilogue ----
#pragma unroll
    for (int mt = 0; mt < 2; mt++) {
        const int r0 = rowBase + wm + mt * 16 + g;
        const int r1 = r0 + 8;
#pragma unroll
        for (int nt = 0; nt < 8; nt++) {
            const int cb = wn + nt * 8 + tg * 2;
            float v0 = acc[mt][nt][0], v1 = acc[mt][nt][1];
            float v2 = acc[mt][nt][2], v3 = acc[mt][nt][3];
            if (bias) {
                const float bb0 = bias[cb], bb1 = bias[cb + 1];
                v0 += bb0; v1 += bb1; v2 += bb0; v3 += bb1;
            }
            if (r0 < M) {
                if (add) {
                    const float2 s = *(const float2*)(add + (size_t)r0 * HID + cb);
                    v0 += s.x; v1 += s.y;
                }
                if (relu) { v0 = fmaxf(v0, 0.f); v1 = fmaxf(v1, 0.f); }
                *(float2*)(C + (size_t)r0 * HID + cb) = make_float2(v0, v1);
            }
            if (r1 < M) {
                if (add) {
                    const float2 s = *(const float2*)(add + (size_t)r1 * HID + cb);
                    v2 += s.x; v3 += s.y;
                }
                if (relu) { v2 = fmaxf(v2, 0.f); v3 = fmaxf(v3, 0.f); }
                *(float2*)(C + (size_t)r1 * HID + cb) = make_float2(v2, v3);
            }
        }
    }
}

// fused triple projection: y=0 -> z@Wd, y=1 -> z@Ws, y=2 -> z@W1a
__global__ __launch_bounds__(256, 2) void gemm3_kernel(
    const float* __restrict__ z, const float* __restrict__ Wm,
    const float* __restrict__ W1, int M)
{
    const float* W;
    float* C;
    if (blockIdx.y == 0)      { W = Wm;             C = g_A; }
    else if (blockIdx.y == 1) { W = Wm + 128 * HID; C = g_B; }
    else                      { W = W1;             C = g_R; }
    gemm_body(z, W, nullptr, nullptr, C, M, 0, blockIdx.x * 128);
}

__global__ __launch_bounds__(256, 2) void gemm1_kernel(
    const float* __restrict__ A, const float* __restrict__ W,
    const float* __restrict__ add, const float* __restrict__ bias,
    float* __restrict__ C, int M, int relu)
{
    gemm_body(A, W, add, bias, C, M, relu, blockIdx.x * 128);
}

// ------------------------- CSR build -------------------------
__global__ void zero_deg_kernel(int nNodes)
{
    int i = blockIdx.x * blockDim.x + threadIdx.x;
    if (i < nNodes) g_deg[i] = 0;
}

__global__ void deg_kernel(const int* __restrict__ dst, int nE)
{
    int e = blockIdx.x * blockDim.x + threadIdx.x;
    if (e < nE) atomicAdd(&g_deg[dst[e]], 1);
}

__global__ __launch_bounds__(1024) void scan_kernel(int nNodes)
{
    __shared__ int warpPre[32];
    __shared__ int s_carry;
    const int tid = threadIdx.x;
    const int lane = tid & 31;
    const int wid = tid >> 5;
    if (tid == 0) s_carry = 0;
    __syncthreads();
    const int nChunks = (nNodes + 1023) >> 10;
    for (int c = 0; c < nChunks; c++) {
        const int i = (c << 10) + tid;
        const int v = (i < nNodes) ? g_deg[i] : 0;
        int incl = v;
#pragma unroll
        for (int o = 1; o < 32; o <<= 1) {
            int t = __shfl_up_sync(0xffffffffu, incl, o);
            if (lane >= o) incl += t;
        }
        if (lane == 31) warpPre[wid] = incl;
        __syncthreads();
        if (wid == 0) {
            int ws = warpPre[lane];
            int wincl = ws;
#pragma unroll
            for (int o = 1; o < 32; o <<= 1) {
                int t = __shfl_up_sync(0xffffffffu, wincl, o);
                if (lane >= o) wincl += t;
            }
            warpPre[lane] = wincl - ws;
        }
        __syncthreads();
        const int excl = s_carry + warpPre[wid] + incl - v;
        if (i < nNodes) { g_off[i] = excl; g_cur[i] = excl; }
        __syncthreads();
        if (tid == 1023) s_carry = excl + v;
        __syncthreads();
    }
    if (tid == 0) g_off[nNodes] = s_carry;
}

__global__ void scatter_kernel(const int* __restrict__ dst, int nE)
{
    int e = blockIdx.x * blockDim.x + threadIdx.x;
    if (e < nE) {
        int p = atomicAdd(&g_cur[dst[e]], 1);
        g_csr[p] = e;
    }
}

// ------------------------- per-node gather-max -------------------------
__global__ __launch_bounds__(256) void agg_kernel(
    const int* __restrict__ src, const float* __restrict__ ew,
    const float* __restrict__ Wm, const float* __restrict__ bm,
    int nNodes)
{
    const int warpId = (blockIdx.x * blockDim.x + threadIdx.x) >> 5;
    const int lane = threadIdx.x & 31;
    if (warpId >= nNodes) return;
    const int n = warpId;
    const float4 ww4 = *(const float4*)(Wm + 256 * HID + lane * 4);
    const int s0 = g_off[n], s1 = g_off[n + 1];
    float4 m = make_float4(-FLT_MAX, -FLT_MAX, -FLT_MAX, -FLT_MAX);
    for (int base = s0; base < s1; base += 32) {
        const int idx = base + lane;
        int sv = 0; float wv = 0.f;
        if (idx < s1) {
            const int e = g_csr[idx];
            sv = src[e];
            wv = ew[e];
        }
        const int cnt = min(32, s1 - base);
        for (int j = 0; j < cnt; j++) {
            const int sj = __shfl_sync(0xffffffffu, sv, j);
            const float wj = __shfl_sync(0xffffffffu, wv, j);
            const float4 b4 = *(const float4*)(g_B + (size_t)sj * HID + lane * 4);
            m.x = fmaxf(m.x, fmaf(wj, ww4.x, b4.x));
            m.y = fmaxf(m.y, fmaf(wj, ww4.y, b4.y));
            m.z = fmaxf(m.z, fmaf(wj, ww4.z, b4.z));
            m.w = fmaxf(m.w, fmaf(wj, ww4.w, b4.w));
        }
    }
    float4 o;
    if (s1 > s0) {
        const float4 a4 = *(const float4*)(g_A + (size_t)n * HID + lane * 4);
        const float4 bm4 = *(const float4*)(bm + lane * 4);
        o = make_float4(a4.x + bm4.x + m.x, a4.y + bm4.y + m.y,
                        a4.z + bm4.z + m.z, a4.w + bm4.w + m.w);
    } else {
        o = make_float4(0.f, 0.f, 0.f, 0.f);
    }
    *(float4*)(g_agg + (size_t)n * HID + lane * 4) = o;
}

// ------------------------- launch -------------------------
extern "C" void kernel_launch(void* const* d_in, const int* in_sizes, int n_in,
                              void* d_out, int out_size)
{
    const float* z   = (const float*)d_in[0];
    const float* ew  = (const float*)d_in[1];
    const int*   esrc= (const int*)d_in[2];
    const int*   edst= (const int*)d_in[3];
    const float* Wm  = (const float*)d_in[4];
    const float* bm  = (const float*)d_in[5];
    const float* W1  = (const float*)d_in[6];
    const float* b1  = (const float*)d_in[7];
    const float* W2  = (const float*)d_in[8];
    const float* b2  = (const float*)d_in[9];
    float* out = (float*)d_out;

    const int nNodes = in_sizes[0] / HID;
    const int nEdges = in_sizes[1];

    float *pAgg, *pHid, *pR;
    cudaGetSymbolAddress((void**)&pAgg, g_agg);
    cudaGetSymbolAddress((void**)&pHid, g_hid);
    cudaGetSymbolAddress((void**)&pR,   g_R);

    cudaFuncSetAttribute(gemm3_kernel, cudaFuncAttributeMaxDynamicSharedMemorySize, GEMM_SMEM_BYTES);
    cudaFuncSetAttribute(gemm1_kernel, cudaFuncAttributeMaxDynamicSharedMemorySize, GEMM_SMEM_BYTES);

    const int gemmGrid = (nNodes + 127) / 128;
    const int edgeGrid = (nEdges + 255) / 256;
    const int nodeGrid = (nNodes + 255) / 256;
    const int aggGrid  = (nNodes + 7) / 8;

    // CSR build
    zero_deg_kernel<<<nodeGrid, 256>>>(nNodes);
    deg_kernel<<<edgeGrid, 256>>>(edst, nEdges);
    scan_kernel<<<1, 1024>>>(nNodes);
    scatter_kernel<<<edgeGrid, 256>>>(edst, nEdges);

    // fused projections on tensor cores (tf32 mma.sync): g_A = z@Wd, g_B = z@Ws, g_R = z@W1a
    gemm3_kernel<<<dim3(gemmGrid, 3), 256, GEMM_SMEM_BYTES>>>(z, Wm, W1, nNodes);

    // segment max (gather form)
    agg_kernel<<<aggGrid, 256>>>(esrc, ew, Wm, bm, nNodes);

    // hidden = relu(R + agg@W1b + b1)
    gemm1_kernel<<<gemmGrid, 256, GEMM_SMEM_BYTES>>>(pAgg, W1 + 128 * HID, pR, b1, pHid, nNodes, 1);
    // out = hidden@W2 + b2
    gemm1_kernel<<<gemmGrid, 256, GEMM_SMEM_BYTES>>>(pHid, W2, nullptr, b2, out, nNodes, 0);
}

// round 5
// speedup vs baseline: 2.5015x; 1.4652x over previous
#include <cuda_runtime.h>
#include <math.h>
#include <float.h>
#include <stdint.h>

#define HID 128
#define MAX_NODES 50000
#define MAX_EDGES 800000

// ------------------------- scratch (static, no allocs) -------------------------
__device__ float g_A[MAX_NODES * HID];     // z @ Wd
__device__ float g_B[MAX_NODES * HID];     // z @ Ws
__device__ float g_agg[MAX_NODES * HID];
__device__ int   g_deg[MAX_NODES];
__device__ int   g_off[MAX_NODES + 1];
__device__ int   g_cur[MAX_NODES];
__device__ int   g_csr[MAX_EDGES];

// ------------------------- tf32 helpers (sm_80+ baseline PTX only) -------------------------
__device__ __forceinline__ uint32_t f2tf(float f) {
    uint32_t u;
    asm("cvt.rna.tf32.f32 %0, %1;" : "=r"(u) : "f"(f));
    return u;
}

__device__ __forceinline__ void mma_tf32(float* c, const uint32_t* a, uint32_t b0, uint32_t b1) {
    asm volatile(
        "mma.sync.aligned.m16n8k8.row.col.f32.tf32.tf32.f32 "
        "{%0,%1,%2,%3}, {%4,%5,%6,%7}, {%8,%9}, {%0,%1,%2,%3};"
        : "+f"(c[0]), "+f"(c[1]), "+f"(c[2]), "+f"(c[3])
        : "r"(a[0]), "r"(a[1]), "r"(a[2]), "r"(a[3]), "r"(b0), "r"(b1));
}

// tiling: CTA = 256 thr = 8 warps (4M x 2N), tile 128(M) x 128(N)
// warp tile 32x64: acc[2 mt][8 nt][4]
#define PAF 132    // full-A / hid pitch (132 % 32 == 4 -> frag loads conflict-free)
#define PAC 68     // chunk-A pitch (68 % 32 == 4)
#define PB  136    // B pitch, k-major (136 % 32 == 8 -> frag loads conflict-free)

// ------------------------- compute core: 8 k8-steps over one 64-K chunk -------------------------
__device__ __forceinline__ void mma_chunk(
    float acc[2][8][4], const uint32_t* __restrict__ Asm, int apitch, int acolBase,
    const uint32_t* __restrict__ Bsm, int wm, int wn, int g, int tg)
{
#pragma unroll
    for (int kk = 0; kk < 64; kk += 8) {
        uint32_t a[2][4];
#pragma unroll
        for (int mt = 0; mt < 2; mt++) {
            const uint32_t* ap = Asm + (wm + mt * 16 + g) * apitch + acolBase + kk + tg;
            a[mt][0] = ap[0];
            a[mt][1] = ap[8 * apitch];
            a[mt][2] = ap[4];
            a[mt][3] = ap[8 * apitch + 4];
        }
#pragma unroll
        for (int nt = 0; nt < 8; nt++) {
            const uint32_t b0 = Bsm[(kk + tg) * PB + wn + nt * 8 + g];
            const uint32_t b1 = Bsm[(kk + tg + 4) * PB + wn + nt * 8 + g];
            mma_tf32(acc[0][nt], a[0], b0, b1);
            mma_tf32(acc[1][nt], a[1], b0, b1);
        }
    }
}

// ------------------------- gemm2: load z tile once, emit g_A = z@Wd, g_B = z@Ws -------------------------
#define GEMM2_SMEM ((128 * PAF + 64 * PB) * 4)   // 67584 + 34816 = 102400 B -> 2 CTA/SM

__global__ __launch_bounds__(256, 2) void gemm2_kernel(
    const float* __restrict__ z, const float* __restrict__ Wm, int M)
{
    extern __shared__ uint32_t sm[];
    uint32_t* As = sm;                  // [128][PAF] full K=128
    uint32_t* Bs = sm + 128 * PAF;      // [64][PB] one K-chunk

    const int tid  = threadIdx.x;
    const int wid  = tid >> 5;
    const int lane = tid & 31;
    const int g    = lane >> 2;
    const int tg   = lane & 3;
    const int wm   = (wid & 3) << 5;
    const int wn   = (wid >> 2) << 6;
    const int rowBase = blockIdx.x * 128;

    // load full A tile (128 x 128), cvt tf32
#pragma unroll
    for (int it = 0; it < 16; it++) {
        const int i = it * 256 + tid;
        const int row = i >> 5;
        const int c4  = (i & 31) << 2;
        const int gr = rowBase + row;
        float4 v = make_float4(0.f, 0.f, 0.f, 0.f);
        if (gr < M) v = *(const float4*)(z + (size_t)gr * HID + c4);
        uint32_t* p = As + row * PAF + c4;
        p[0] = f2tf(v.x); p[1] = f2tf(v.y); p[2] = f2tf(v.z); p[3] = f2tf(v.w);
    }

    for (int w = 0; w < 2; w++) {
        const float* W = Wm + (size_t)w * 128 * HID;
        float acc[2][8][4];
#pragma unroll
        for (int mt = 0; mt < 2; mt++)
#pragma unroll
            for (int nt = 0; nt < 8; nt++)
#pragma unroll
                for (int i = 0; i < 4; i++) acc[mt][nt][i] = 0.f;

        for (int chunk = 0; chunk < 2; chunk++) {
#pragma unroll
            for (int it = 0; it < 8; it++) {
                const int i = it * 256 + tid;
                const int k  = i >> 5;
                const int n4 = (i & 31) << 2;
                const float4 v = *(const float4*)(W + (size_t)(chunk * 64 + k) * HID + n4);
                uint32_t* p = Bs + k * PB + n4;
                p[0] = f2tf(v.x); p[1] = f2tf(v.y); p[2] = f2tf(v.z); p[3] = f2tf(v.w);
            }
            __syncthreads();
            mma_chunk(acc, As, PAF, chunk * 64, Bs, wm, wn, g, tg);
            __syncthreads();
        }

        float* C = w ? g_B : g_A;
#pragma unroll
        for (int mt = 0; mt < 2; mt++) {
            const int r0 = rowBase + wm + mt * 16 + g;
            const int r1 = r0 + 8;
#pragma unroll
            for (int nt = 0; nt < 8; nt++) {
                const int cb = wn + nt * 8 + tg * 2;
                if (r0 < M) *(float2*)(C + (size_t)r0 * HID + cb) =
                    make_float2(acc[mt][nt][0], acc[mt][nt][1]);
                if (r1 < M) *(float2*)(C + (size_t)r1 * HID + cb) =
                    make_float2(acc[mt][nt][2], acc[mt][nt][3]);
            }
        }
    }
}

// ------------------------- fused MLP: hidden = relu([z|agg]@W1 + b1); out = hidden@W2 + b2 -------------------------
// smem layout (overlapped):
//   stage1: As1 [0, 34816) + Bs1 [34816, 69632)
//   stage2: hid [0, 67584) (clobbers As1/Bs1 after stage-1 final sync) + Bs2 [69632, 104448)
#define FUSED_SMEM (104448)

__global__ __launch_bounds__(256, 2) void fused_mlp_kernel(
    const float* __restrict__ z, const float* __restrict__ W1,
    const float* __restrict__ b1, const float* __restrict__ W2,
    const float* __restrict__ b2, float* __restrict__ out, int M)
{
    extern __shared__ uint32_t sm[];
    uint32_t* As1 = sm;                 // [128][PAC]
    uint32_t* Bs1 = sm + 8704;          // [64][PB]
    uint32_t* hid = sm;                 // [128][PAF]
    uint32_t* Bs2 = sm + 17408;         // [64][PB]

    const int tid  = threadIdx.x;
    const int wid  = tid >> 5;
    const int lane = tid & 31;
    const int g    = lane >> 2;
    const int tg   = lane & 3;
    const int wm   = (wid & 3) << 5;
    const int wn   = (wid >> 2) << 6;
    const int rowBase = blockIdx.x * 128;

    float acc[2][8][4];
#pragma unroll
    for (int mt = 0; mt < 2; mt++)
#pragma unroll
        for (int nt = 0; nt < 8; nt++)
#pragma unroll
            for (int i = 0; i < 4; i++) acc[mt][nt][i] = 0.f;

    // ---- stage 1: K=256 over [z | agg] with W1[256][128] ----
    for (int chunk = 0; chunk < 4; chunk++) {
        const float* Asrc = (chunk < 2) ? z : g_agg;
        const int kloc = (chunk & 1) * 64;
        // A chunk [128 rows][64 k]
#pragma unroll
        for (int it = 0; it < 8; it++) {
            const int i = it * 256 + tid;
            const int row = i >> 4;
            const int c4  = (i & 15) << 2;
            const int gr = rowBase + row;
            float4 v = make_float4(0.f, 0.f, 0.f, 0.f);
            if (gr < M) v = *(const float4*)(Asrc + (size_t)gr * HID + kloc + c4);
            uint32_t* p = As1 + row * PAC + c4;
            p[0] = f2tf(v.x); p[1] = f2tf(v.y); p[2] = f2tf(v.z); p[3] = f2tf(v.w);
        }
        // B chunk from W1 rows chunk*64 .. +63
#pragma unroll
        for (int it = 0; it < 8; it++) {
            const int i = it * 256 + tid;
            const int k  = i >> 5;
            const int n4 = (i & 31) << 2;
            const float4 v = *(const float4*)(W1 + (size_t)(chunk * 64 + k) * HID + n4);
            uint32_t* p = Bs1 + k * PB + n4;
            p[0] = f2tf(v.x); p[1] = f2tf(v.y); p[2] = f2tf(v.z); p[3] = f2tf(v.w);
        }
        __syncthreads();
        mma_chunk(acc, As1, PAC, 0, Bs1, wm, wn, g, tg);
        __syncthreads();
    }

    // ---- stage-1 epilogue: hid = tf32(relu(acc + b1)), clobbers As1/Bs1 ----
#pragma unroll
    for (int mt = 0; mt < 2; mt++) {
        const int lr0 = wm + mt * 16 + g;
        const int lr1 = lr0 + 8;
#pragma unroll
        for (int nt = 0; nt < 8; nt++) {
            const int cb = wn + nt * 8 + tg * 2;
            const float bb0 = b1[cb], bb1 = b1[cb + 1];
            uint2 v0, v1;
            v0.x = f2tf(fmaxf(acc[mt][nt][0] + bb0, 0.f));
            v0.y = f2tf(fmaxf(acc[mt][nt][1] + bb1, 0.f));
            v1.x = f2tf(fmaxf(acc[mt][nt][2] + bb0, 0.f));
            v1.y = f2tf(fmaxf(acc[mt][nt][3] + bb1, 0.f));
            *(uint2*)(hid + lr0 * PAF + cb) = v0;
            *(uint2*)(hid + lr1 * PAF + cb) = v1;
        }
    }
    __syncthreads();

    // ---- stage 2: out = hid @ W2 + b2 ----
#pragma unroll
    for (int mt = 0; mt < 2; mt++)
#pragma unroll
        for (int nt = 0; nt < 8; nt++)
#pragma unroll
            for (int i = 0; i < 4; i++) acc[mt][nt][i] = 0.f;

    for (int chunk = 0; chunk < 2; chunk++) {
#pragma unroll
        for (int it = 0; it < 8; it++) {
            const int i = it * 256 + tid;
            const int k  = i >> 5;
            const int n4 = (i & 31) << 2;
            const float4 v = *(const float4*)(W2 + (size_t)(chunk * 64 + k) * HID + n4);
            uint32_t* p = Bs2 + k * PB + n4;
            p[0] = f2tf(v.x); p[1] = f2tf(v.y); p[2] = f2tf(v.z); p[3] = f2tf(v.w);
        }
        __syncthreads();
        mma_chunk(acc, hid, PAF, chunk * 64, Bs2, wm, wn, g, tg);
        __syncthreads();
    }

#pragma unroll
    for (int mt = 0; mt < 2; mt++) {
        const int r0 = rowBase + wm + mt * 16 + g;
        const int r1 = r0 + 8;
#pragma unroll
        for (int nt = 0; nt < 8; nt++) {
            const int cb = wn + nt * 8 + tg * 2;
            const float bb0 = b2[cb], bb1 = b2[cb + 1];
            if (r0 < M) *(float2*)(out + (size_t)r0 * HID + cb) =
                make_float2(acc[mt][nt][0] + bb0, acc[mt][nt][1] + bb1);
            if (r1 < M) *(float2*)(out + (size_t)r1 * HID + cb) =
                make_float2(acc[mt][nt][2] + bb0, acc[mt][nt][3] + bb1);
        }
    }
}

// ------------------------- CSR build -------------------------
__global__ void zero_deg_kernel(int nNodes)
{
    int i = blockIdx.x * blockDim.x + threadIdx.x;
    if (i < nNodes) g_deg[i] = 0;
}

__global__ void deg_kernel(const int* __restrict__ dst, int nE)
{
    int e = blockIdx.x * blockDim.x + threadIdx.x;
    if (e < nE) atomicAdd(&g_deg[dst[e]], 1);
}

__global__ __launch_bounds__(1024) void scan_kernel(int nNodes)
{
    __shared__ int warpPre[32];
    __shared__ int s_carry;
    const int tid = threadIdx.x;
    const int lane = tid & 31;
    const int wid = tid >> 5;
    if (tid == 0) s_carry = 0;
    __syncthreads();
    const int nChunks = (nNodes + 1023) >> 10;
    for (int c = 0; c < nChunks; c++) {
        const int i = (c << 10) + tid;
        const int v = (i < nNodes) ? g_deg[i] : 0;
        int incl = v;
#pragma unroll
        for (int o = 1; o < 32; o <<= 1) {
            int t = __shfl_up_sync(0xffffffffu, incl, o);
            if (lane >= o) incl += t;
        }
        if (lane == 31) warpPre[wid] = incl;
        __syncthreads();
        if (wid == 0) {
            int ws = warpPre[lane];
            int wincl = ws;
#pragma unroll
            for (int o = 1; o < 32; o <<= 1) {
                int t = __shfl_up_sync(0xffffffffu, wincl, o);
                if (lane >= o) wincl += t;
            }
            warpPre[lane] = wincl - ws;
        }
        __syncthreads();
        const int excl = s_carry + warpPre[wid] + incl - v;
        if (i < nNodes) { g_off[i] = excl; g_cur[i] = excl; }
        __syncthreads();
        if (tid == 1023) s_carry = excl + v;
        __syncthreads();
    }
    if (tid == 0) g_off[nNodes] = s_carry;
}

__global__ void scatter_kernel(const int* __restrict__ dst, int nE)
{
    int e = blockIdx.x * blockDim.x + threadIdx.x;
    if (e < nE) {
        int p = atomicAdd(&g_cur[dst[e]], 1);
        g_csr[p] = e;
    }
}

// ------------------------- per-node gather-max -------------------------
__global__ __launch_bounds__(256) void agg_kernel(
    const int* __restrict__ src, const float* __restrict__ ew,
    const float* __restrict__ Wm, const float* __restrict__ bm,
    int nNodes)
{
    const int warpId = (blockIdx.x * blockDim.x + threadIdx.x) >> 5;
    const int lane = threadIdx.x & 31;
    if (warpId >= nNodes) return;
    const int n = warpId;
    const float4 ww4 = *(const float4*)(Wm + 256 * HID + lane * 4);
    const int s0 = g_off[n], s1 = g_off[n + 1];
    float4 m = make_float4(-FLT_MAX, -FLT_MAX, -FLT_MAX, -FLT_MAX);
    for (int base = s0; base < s1; base += 32) {
        const int idx = base + lane;
        int sv = 0; float wv = 0.f;
        if (idx < s1) {
            const int e = g_csr[idx];
            sv = src[e];
            wv = ew[e];
        }
        const int cnt = min(32, s1 - base);
        for (int j = 0; j < cnt; j++) {
            const int sj = __shfl_sync(0xffffffffu, sv, j);
            const float wj = __shfl_sync(0xffffffffu, wv, j);
            const float4 b4 = *(const float4*)(g_B + (size_t)sj * HID + lane * 4);
            m.x = fmaxf(m.x, fmaf(wj, ww4.x, b4.x));
            m.y = fmaxf(m.y, fmaf(wj, ww4.y, b4.y));
            m.z = fmaxf(m.z, fmaf(wj, ww4.z, b4.z));
            m.w = fmaxf(m.w, fmaf(wj, ww4.w, b4.w));
        }
    }
    float4 o;
    if (s1 > s0) {
        const float4 a4 = *(const float4*)(g_A + (size_t)n * HID + lane * 4);
        const float4 bm4 = *(const float4*)(bm + lane * 4);
        o = make_float4(a4.x + bm4.x + m.x, a4.y + bm4.y + m.y,
                        a4.z + bm4.z + m.z, a4.w + bm4.w + m.w);
    } else {
        o = make_float4(0.f, 0.f, 0.f, 0.f);
    }
    *(float4*)(g_agg + (size_t)n * HID + lane * 4) = o;
}

// ------------------------- launch -------------------------
extern "C" void kernel_launch(void* const* d_in, const int* in_sizes, int n_in,
                              void* d_out, int out_size)
{
    const float* z   = (const float*)d_in[0];
    const float* ew  = (const float*)d_in[1];
    const int*   esrc= (const int*)d_in[2];
    const int*   edst= (const int*)d_in[3];
    const float* Wm  = (const float*)d_in[4];
    const float* bm  = (const float*)d_in[5];
    const float* W1  = (const float*)d_in[6];
    const float* b1  = (const float*)d_in[7];
    const float* W2  = (const float*)d_in[8];
    const float* b2  = (const float*)d_in[9];
    float* out = (float*)d_out;

    const int nNodes = in_sizes[0] / HID;
    const int nEdges = in_sizes[1];

    cudaFuncSetAttribute(gemm2_kernel, cudaFuncAttributeMaxDynamicSharedMemorySize, GEMM2_SMEM);
    cudaFuncSetAttribute(fused_mlp_kernel, cudaFuncAttributeMaxDynamicSharedMemorySize, FUSED_SMEM);

    const int gemmGrid = (nNodes + 127) / 128;
    const int edgeGrid = (nEdges + 255) / 256;
    const int nodeGrid = (nNodes + 255) / 256;
    const int aggGrid  = (nNodes + 7) / 8;

    // CSR build
    zero_deg_kernel<<<nodeGrid, 256>>>(nNodes);
    deg_kernel<<<edgeGrid, 256>>>(edst, nEdges);
    scan_kernel<<<1, 1024>>>(nNodes);
    scatter_kernel<<<edgeGrid, 256>>>(edst, nEdges);

    // shared-A dual projection: g_A = z@Wd, g_B = z@Ws
    gemm2_kernel<<<gemmGrid, 256, GEMM2_SMEM>>>(z, Wm, nNodes);

    // segment max (gather form)
    agg_kernel<<<aggGrid, 256>>>(esrc, ew, Wm, bm, nNodes);

    // fused: hidden = relu([z|agg]@W1 + b1); out = hidden@W2 + b2
    fused_mlp_kernel<<<gemmGrid, 256, FUSED_SMEM>>>(z, W1, b1, W2, b2, out, nNodes);
}

// round 6
// speedup vs baseline: 2.6934x; 1.0767x over previous
#include <cuda_runtime.h>
#include <math.h>
#include <float.h>
#include <stdint.h>

#define HID 128
#define MAX_NODES 50000
#define MAX_EDGES 800000

// ------------------------- scratch (static, no allocs) -------------------------
__device__ float g_A[MAX_NODES * HID];     // z @ Wd
__device__ float g_B[MAX_NODES * HID];     // z @ Ws
__device__ float g_agg[MAX_NODES * HID];
__device__ int   g_deg[MAX_NODES];
__device__ int   g_off[MAX_NODES + 1];
__device__ int   g_cur[MAX_NODES];
__device__ int   g_csr[MAX_EDGES];

// ------------------------- tf32 helpers (sm_80+ baseline PTX only) -------------------------
__device__ __forceinline__ uint32_t f2tf(float f) {
    uint32_t u;
    asm("cvt.rna.tf32.f32 %0, %1;" : "=r"(u) : "f"(f));
    return u;
}

__device__ __forceinline__ void mma_tf32(float* c, const uint32_t* a, uint32_t b0, uint32_t b1) {
    asm volatile(
        "mma.sync.aligned.m16n8k8.row.col.f32.tf32.tf32.f32 "
        "{%0,%1,%2,%3}, {%4,%5,%6,%7}, {%8,%9}, {%0,%1,%2,%3};"
        : "+f"(c[0]), "+f"(c[1]), "+f"(c[2]), "+f"(c[3])
        : "r"(a[0]), "r"(a[1]), "r"(a[2]), "r"(a[3]), "r"(b0), "r"(b1));
}

// tiling: CTA = 256 thr = 8 warps (4M x 2N), tile 128(M) x 128(N)
#define PAF 132    // full-A / hid pitch (132 % 32 == 4 -> frag loads conflict-free)
#define PAC 68     // chunk-A pitch (68 % 32 == 4)
#define PB  136    // B pitch, k-major (136 % 32 == 8 -> frag loads conflict-free)

// ------------------------- compute core: 8 k8-steps over one 64-K chunk -------------------------
__device__ __forceinline__ void mma_chunk(
    float acc[2][8][4], const uint32_t* __restrict__ Asm, int apitch, int acolBase,
    const uint32_t* __restrict__ Bsm, int wm, int wn, int g, int tg)
{
#pragma unroll
    for (int kk = 0; kk < 64; kk += 8) {
        uint32_t a[2][4];
#pragma unroll
        for (int mt = 0; mt < 2; mt++) {
            const uint32_t* ap = Asm + (wm + mt * 16 + g) * apitch + acolBase + kk + tg;
            a[mt][0] = ap[0];
            a[mt][1] = ap[8 * apitch];
            a[mt][2] = ap[4];
            a[mt][3] = ap[8 * apitch + 4];
        }
#pragma unroll
        for (int nt = 0; nt < 8; nt++) {
            const uint32_t b0 = Bsm[(kk + tg) * PB + wn + nt * 8 + g];
            const uint32_t b1 = Bsm[(kk + tg + 4) * PB + wn + nt * 8 + g];
            mma_tf32(acc[0][nt], a[0], b0, b1);
            mma_tf32(acc[1][nt], a[1], b0, b1);
        }
    }
}

// ------------------------- gemm2: load z tile once, emit g_A = z@Wd, g_B = z@Ws -------------------------
#define GEMM2_SMEM ((128 * PAF + 64 * PB) * 4)   // 102400 B -> 2 CTA/SM

__global__ __launch_bounds__(256, 2) void gemm2_kernel(
    const float* __restrict__ z, const float* __restrict__ Wm, int M)
{
    extern __shared__ uint32_t sm[];
    uint32_t* As = sm;                  // [128][PAF] full K=128
    uint32_t* Bs = sm + 128 * PAF;      // [64][PB] one K-chunk

    const int tid  = threadIdx.x;
    const int wid  = tid >> 5;
    const int lane = tid & 31;
    const int g    = lane >> 2;
    const int tg   = lane & 3;
    const int wm   = (wid & 3) << 5;
    const int wn   = (wid >> 2) << 6;
    const int rowBase = blockIdx.x * 128;

    // load full A tile (128 x 128), cvt tf32
#pragma unroll
    for (int it = 0; it < 16; it++) {
        const int i = it * 256 + tid;
        const int row = i >> 5;
        const int c4  = (i & 31) << 2;
        const int gr = rowBase + row;
        float4 v = make_float4(0.f, 0.f, 0.f, 0.f);
        if (gr < M) v = *(const float4*)(z + (size_t)gr * HID + c4);
        uint32_t* p = As + row * PAF + c4;
        p[0] = f2tf(v.x); p[1] = f2tf(v.y); p[2] = f2tf(v.z); p[3] = f2tf(v.w);
    }

    for (int w = 0; w < 2; w++) {
        const float* W = Wm + (size_t)w * 128 * HID;
        float acc[2][8][4];
#pragma unroll
        for (int mt = 0; mt < 2; mt++)
#pragma unroll
            for (int nt = 0; nt < 8; nt++)
#pragma unroll
                for (int i = 0; i < 4; i++) acc[mt][nt][i] = 0.f;

        for (int chunk = 0; chunk < 2; chunk++) {
#pragma unroll
            for (int it = 0; it < 8; it++) {
                const int i = it * 256 + tid;
                const int k  = i >> 5;
                const int n4 = (i & 31) << 2;
                const float4 v = *(const float4*)(W + (size_t)(chunk * 64 + k) * HID + n4);
                uint32_t* p = Bs + k * PB + n4;
                p[0] = f2tf(v.x); p[1] = f2tf(v.y); p[2] = f2tf(v.z); p[3] = f2tf(v.w);
            }
            __syncthreads();
            mma_chunk(acc, As, PAF, chunk * 64, Bs, wm, wn, g, tg);
            __syncthreads();
        }

        float* C = w ? g_B : g_A;
#pragma unroll
        for (int mt = 0; mt < 2; mt++) {
            const int r0 = rowBase + wm + mt * 16 + g;
            const int r1 = r0 + 8;
#pragma unroll
            for (int nt = 0; nt < 8; nt++) {
                const int cb = wn + nt * 8 + tg * 2;
                if (r0 < M) *(float2*)(C + (size_t)r0 * HID + cb) =
                    make_float2(acc[mt][nt][0], acc[mt][nt][1]);
                if (r1 < M) *(float2*)(C + (size_t)r1 * HID + cb) =
                    make_float2(acc[mt][nt][2], acc[mt][nt][3]);
            }
        }
    }
}

// ------------------------- fused MLP: hidden = relu([z|agg]@W1 + b1); out = hidden@W2 + b2 -------------------------
#define FUSED_SMEM (104448)

__global__ __launch_bounds__(256, 2) void fused_mlp_kernel(
    const float* __restrict__ z, const float* __restrict__ W1,
    const float* __restrict__ b1, const float* __restrict__ W2,
    const float* __restrict__ b2, float* __restrict__ out, int M)
{
    extern __shared__ uint32_t sm[];
    uint32_t* As1 = sm;                 // [128][PAC]
    uint32_t* Bs1 = sm + 8704;          // [64][PB]
    uint32_t* hid = sm;                 // [128][PAF] (clobbers As1/Bs1)
    uint32_t* Bs2 = sm + 17408;         // [64][PB]

    const int tid  = threadIdx.x;
    const int wid  = tid >> 5;
    const int lane = tid & 31;
    const int g    = lane >> 2;
    const int tg   = lane & 3;
    const int wm   = (wid & 3) << 5;
    const int wn   = (wid >> 2) << 6;
    const int rowBase = blockIdx.x * 128;

    float acc[2][8][4];
#pragma unroll
    for (int mt = 0; mt < 2; mt++)
#pragma unroll
        for (int nt = 0; nt < 8; nt++)
#pragma unroll
            for (int i = 0; i < 4; i++) acc[mt][nt][i] = 0.f;

    // ---- stage 1: K=256 over [z | agg] with W1[256][128] ----
    for (int chunk = 0; chunk < 4; chunk++) {
        const float* Asrc = (chunk < 2) ? z : g_agg;
        const int kloc = (chunk & 1) * 64;
#pragma unroll
        for (int it = 0; it < 8; it++) {
            const int i = it * 256 + tid;
            const int row = i >> 4;
            const int c4  = (i & 15) << 2;
            const int gr = rowBase + row;
            float4 v = make_float4(0.f, 0.f, 0.f, 0.f);
            if (gr < M) v = *(const float4*)(Asrc + (size_t)gr * HID + kloc + c4);
            uint32_t* p = As1 + row * PAC + c4;
            p[0] = f2tf(v.x); p[1] = f2tf(v.y); p[2] = f2tf(v.z); p[3] = f2tf(v.w);
        }
#pragma unroll
        for (int it = 0; it < 8; it++) {
            const int i = it * 256 + tid;
            const int k  = i >> 5;
            const int n4 = (i & 31) << 2;
            const float4 v = *(const float4*)(W1 + (size_t)(chunk * 64 + k) * HID + n4);
            uint32_t* p = Bs1 + k * PB + n4;
            p[0] = f2tf(v.x); p[1] = f2tf(v.y); p[2] = f2tf(v.z); p[3] = f2tf(v.w);
        }
        __syncthreads();
        mma_chunk(acc, As1, PAC, 0, Bs1, wm, wn, g, tg);
        __syncthreads();
    }

    // ---- stage-1 epilogue: hid = tf32(relu(acc + b1)) ----
#pragma unroll
    for (int mt = 0; mt < 2; mt++) {
        const int lr0 = wm + mt * 16 + g;
        const int lr1 = lr0 + 8;
#pragma unroll
        for (int nt = 0; nt < 8; nt++) {
            const int cb = wn + nt * 8 + tg * 2;
            const float bb0 = b1[cb], bb1 = b1[cb + 1];
            uint2 v0, v1;
            v0.x = f2tf(fmaxf(acc[mt][nt][0] + bb0, 0.f));
            v0.y = f2tf(fmaxf(acc[mt][nt][1] + bb1, 0.f));
            v1.x = f2tf(fmaxf(acc[mt][nt][2] + bb0, 0.f));
            v1.y = f2tf(fmaxf(acc[mt][nt][3] + bb1, 0.f));
            *(uint2*)(hid + lr0 * PAF + cb) = v0;
            *(uint2*)(hid + lr1 * PAF + cb) = v1;
        }
    }
    __syncthreads();

    // ---- stage 2: out = hid @ W2 + b2 ----
#pragma unroll
    for (int mt = 0; mt < 2; mt++)
#pragma unroll
        for (int nt = 0; nt < 8; nt++)
#pragma unroll
            for (int i = 0; i < 4; i++) acc[mt][nt][i] = 0.f;

    for (int chunk = 0; chunk < 2; chunk++) {
#pragma unroll
        for (int it = 0; it < 8; it++) {
            const int i = it * 256 + tid;
            const int k  = i >> 5;
            const int n4 = (i & 31) << 2;
            const float4 v = *(const float4*)(W2 + (size_t)(chunk * 64 + k) * HID + n4);
            uint32_t* p = Bs2 + k * PB + n4;
            p[0] = f2tf(v.x); p[1] = f2tf(v.y); p[2] = f2tf(v.z); p[3] = f2tf(v.w);
        }
        __syncthreads();
        mma_chunk(acc, hid, PAF, chunk * 64, Bs2, wm, wn, g, tg);
        __syncthreads();
    }

#pragma unroll
    for (int mt = 0; mt < 2; mt++) {
        const int r0 = rowBase + wm + mt * 16 + g;
        const int r1 = r0 + 8;
#pragma unroll
        for (int nt = 0; nt < 8; nt++) {
            const int cb = wn + nt * 8 + tg * 2;
            const float bb0 = b2[cb], bb1 = b2[cb + 1];
            if (r0 < M) *(float2*)(out + (size_t)r0 * HID + cb) =
                make_float2(acc[mt][nt][0] + bb0, acc[mt][nt][1] + bb1);
            if (r1 < M) *(float2*)(out + (size_t)r1 * HID + cb) =
                make_float2(acc[mt][nt][2] + bb0, acc[mt][nt][3] + bb1);
        }
    }
}

// ------------------------- CSR build -------------------------
__global__ void zero_deg_kernel(int nNodes)
{
    int i = blockIdx.x * blockDim.x + threadIdx.x;
    if (i < nNodes) g_deg[i] = 0;
}

__global__ void deg_kernel(const int* __restrict__ dst, int nE)
{
    int e = blockIdx.x * blockDim.x + threadIdx.x;
    if (e < nE) atomicAdd(&g_deg[dst[e]], 1);
}

__global__ __launch_bounds__(1024) void scan_kernel(int nNodes)
{
    __shared__ int warpPre[32];
    __shared__ int s_carry;
    const int tid = threadIdx.x;
    const int lane = tid & 31;
    const int wid = tid >> 5;
    if (tid == 0) s_carry = 0;
    __syncthreads();
    const int nChunks = (nNodes + 1023) >> 10;
    for (int c = 0; c < nChunks; c++) {
        const int i = (c << 10) + tid;
        const int v = (i < nNodes) ? g_deg[i] : 0;
        int incl = v;
#pragma unroll
        for (int o = 1; o < 32; o <<= 1) {
            int t = __shfl_up_sync(0xffffffffu, incl, o);
            if (lane >= o) incl += t;
        }
        if (lane == 31) warpPre[wid] = incl;
        __syncthreads();
        if (wid == 0) {
            int ws = warpPre[lane];
            int wincl = ws;
#pragma unroll
            for (int o = 1; o < 32; o <<= 1) {
                int t = __shfl_up_sync(0xffffffffu, wincl, o);
                if (lane >= o) wincl += t;
            }
            warpPre[lane] = wincl - ws;
        }
        __syncthreads();
        const int excl = s_carry + warpPre[wid] + incl - v;
        if (i < nNodes) { g_off[i] = excl; g_cur[i] = excl; }
        __syncthreads();
        if (tid == 1023) s_carry = excl + v;
        __syncthreads();
    }
    if (tid == 0) g_off[nNodes] = s_carry;
}

__global__ void scatter_kernel(const int* __restrict__ dst, int nE)
{
    int e = blockIdx.x * blockDim.x + threadIdx.x;
    if (e < nE) {
        int p = atomicAdd(&g_cur[dst[e]], 1);
        g_csr[p] = e;
    }
}

// ------------------------- per-node gather-max -------------------------
__global__ __launch_bounds__(256) void agg_kernel(
    const int* __restrict__ src, const float* __restrict__ ew,
    const float* __restrict__ Wm, const float* __restrict__ bm,
    int nNodes)
{
    const int warpId = (blockIdx.x * blockDim.x + threadIdx.x) >> 5;
    const int lane = threadIdx.x & 31;
    if (warpId >= nNodes) return;
    const int n = warpId;
    const float4 ww4 = *(const float4*)(Wm + 256 * HID + lane * 4);
    const int s0 = g_off[n], s1 = g_off[n + 1];
    float4 m = make_float4(-FLT_MAX, -FLT_MAX, -FLT_MAX, -FLT_MAX);
    for (int base = s0; base < s1; base += 32) {
        const int idx = base + lane;
        int sv = 0; float wv = 0.f;
        if (idx < s1) {
            const int e = g_csr[idx];
            sv = src[e];
            wv = ew[e];
        }
        const int cnt = min(32, s1 - base);
        for (int j = 0; j < cnt; j++) {
            const int sj = __shfl_sync(0xffffffffu, sv, j);
            const float wj = __shfl_sync(0xffffffffu, wv, j);
            const float4 b4 = *(const float4*)(g_B + (size_t)sj * HID + lane * 4);
            m.x = fmaxf(m.x, fmaf(wj, ww4.x, b4.x));
            m.y = fmaxf(m.y, fmaf(wj, ww4.y, b4.y));
            m.z = fmaxf(m.z, fmaf(wj, ww4.z, b4.z));
            m.w = fmaxf(m.w, fmaf(wj, ww4.w, b4.w));
        }
    }
    float4 o;
    if (s1 > s0) {
        const float4 a4 = *(const float4*)(g_A + (size_t)n * HID + lane * 4);
        const float4 bm4 = *(const float4*)(bm + lane * 4);
        o = make_float4(a4.x + bm4.x + m.x, a4.y + bm4.y + m.y,
                        a4.z + bm4.z + m.z, a4.w + bm4.w + m.w);
    } else {
        o = make_float4(0.f, 0.f, 0.f, 0.f);
    }
    *(float4*)(g_agg + (size_t)n * HID + lane * 4) = o;
}

// ------------------------- launch -------------------------
extern "C" void kernel_launch(void* const* d_in, const int* in_sizes, int n_in,
                              void* d_out, int out_size)
{
    const float* z   = (const float*)d_in[0];
    const float* ew  = (const float*)d_in[1];
    const int*   esrc= (const int*)d_in[2];
    const int*   edst= (const int*)d_in[3];
    const float* Wm  = (const float*)d_in[4];
    const float* bm  = (const float*)d_in[5];
    const float* W1  = (const float*)d_in[6];
    const float* b1  = (const float*)d_in[7];
    const float* W2  = (const float*)d_in[8];
    const float* b2  = (const float*)d_in[9];
    float* out = (float*)d_out;

    const int nNodes = in_sizes[0] / HID;
    const int nEdges = in_sizes[1];

    cudaFuncSetAttribute(gemm2_kernel, cudaFuncAttributeMaxDynamicSharedMemorySize, GEMM2_SMEM);
    cudaFuncSetAttribute(fused_mlp_kernel, cudaFuncAttributeMaxDynamicSharedMemorySize, FUSED_SMEM);

    // lazily-created side stream + fork/join events (host-side objects, no device mem)
    static cudaStream_t s_side = nullptr;
    static cudaEvent_t  s_evFork = nullptr, s_evJoin = nullptr;
    if (!s_side) {
        cudaStreamCreateWithFlags(&s_side, cudaStreamNonBlocking);
        cudaEventCreateWithFlags(&s_evFork, cudaEventDisableTiming);
        cudaEventCreateWithFlags(&s_evJoin, cudaEventDisableTiming);
    }

    const int gemmGrid = (nNodes + 127) / 128;
    const int edgeGrid = (nEdges + 255) / 256;
    const int nodeGrid = (nNodes + 255) / 256;
    const int aggGrid  = (nNodes + 7) / 8;

    // fork: CSR build (edge-only inputs) runs concurrently with gemm2 (z-only inputs)
    cudaEventRecord(s_evFork, 0);
    cudaStreamWaitEvent(s_side, s_evFork, 0);

    // side stream: CSR build
    zero_deg_kernel<<<nodeGrid, 256, 0, s_side>>>(nNodes);
    deg_kernel<<<edgeGrid, 256, 0, s_side>>>(edst, nEdges);
    scan_kernel<<<1, 1024, 0, s_side>>>(nNodes);
    scatter_kernel<<<edgeGrid, 256, 0, s_side>>>(edst, nEdges);
    cudaEventRecord(s_evJoin, s_side);

    // main stream: shared-A dual projection g_A = z@Wd, g_B = z@Ws
    gemm2_kernel<<<gemmGrid, 256, GEMM2_SMEM>>>(z, Wm, nNodes);

    // join: agg needs both CSR and g_A/g_B
    cudaStreamWaitEvent(0, s_evJoin, 0);

    // segment max (gather form)
    agg_kernel<<<aggGrid, 256>>>(esrc, ew, Wm, bm, nNodes);

    // fused: hidden = relu([z|agg]@W1 + b1); out = hidden@W2 + b2
    fused_mlp_kernel<<<gemmGrid, 256, FUSED_SMEM>>>(z, W1, b1, W2, b2, out, nNodes);
}